// round 2
// baseline (speedup 1.0000x reference)
#include <cuda_runtime.h>

#define NBLK 128
#define WPB  4        // warps per block
#define P    4        // batch rows per warp
#define TT   512
#define HH   32

typedef unsigned long long u64;

__device__ __forceinline__ u64 pk2(float a, float b) {
    u64 r; asm("mov.b64 %0,{%1,%2};" : "=l"(r) : "f"(a), "f"(b)); return r;
}
__device__ __forceinline__ void upk2(u64 v, float& a, float& b) {
    asm("mov.b64 {%0,%1},%2;" : "=f"(a), "=f"(b) : "l"(v));
}
__device__ __forceinline__ u64 ffma2(u64 a, u64 b, u64 c) {
    u64 d; asm("fma.rn.f32x2 %0,%1,%2,%3;" : "=l"(d) : "l"(a), "l"(b), "l"(c)); return d;
}
__device__ __forceinline__ u64 fmul2(u64 a, u64 b) {
    u64 d; asm("mul.rn.f32x2 %0,%1,%2;" : "=l"(d) : "l"(a), "l"(b)); return d;
}
__device__ __forceinline__ float ex2f(float x) {
    float y; asm("ex2.approx.f32 %0,%1;" : "=f"(y) : "f"(x)); return y;
}
__device__ __forceinline__ float rcpf(float x) {
    float y; asm("rcp.approx.f32 %0,%1;" : "=f"(y) : "f"(x)); return y;
}
// sigmoid(v) = 1/(1+exp(-v)) via ex2+rcp (~1e-6 accurate)
__device__ __forceinline__ float sigm(float v) {
    return rcpf(1.0f + ex2f(v * -1.4426950408889634f));
}
// tanh(v) = 2/(1+exp(-2v)) - 1
__device__ __forceinline__ float tanhfast(float v) {
    float s = rcpf(1.0f + ex2f(v * -2.8853900817779268f));
    return fmaf(2.0f, s, -1.0f);
}

// one GRU gate update for one batch element, given k-packed partial sums
__device__ __forceinline__ float gru_gate(u64 ar, u64 az, u64 an,
                                          float sr, float sz, float sn,
                                          float bn_h, float hprev) {
    float lo, hi;
    upk2(ar, lo, hi); float r = sigm(lo + hi + sr);
    upk2(az, lo, hi); float z = sigm(lo + hi + sz);
    upk2(an, lo, hi); float hn = lo + hi + bn_h;
    float n = tanhfast(fmaf(r, hn, sn));
    return fmaf(z, hprev - n, n);   // (1-z)*n + z*h
}

__global__ void __launch_bounds__(WPB * 32, 1)
gru_bidir_kernel(const float* __restrict__ x,
                 const float* __restrict__ Wihf, const float* __restrict__ Whhf,
                 const float* __restrict__ bihf, const float* __restrict__ bhhf,
                 const float* __restrict__ Wihb, const float* __restrict__ Whhb,
                 const float* __restrict__ bihb, const float* __restrict__ bhhb,
                 const float* __restrict__ W1,  const float* __restrict__ b1,
                 const float* __restrict__ W2,  const float* __restrict__ b2,
                 float* __restrict__ out)
{
    __shared__ float4 xs[WPB][TT];                         // 32 KB: x staged per warp
    __shared__ __align__(16) float hbuf[WPB][2][P][HH];    // 4 KB: ping-pong hidden (read as u64)
    __shared__ __align__(16) float vbuf[WPB][P][2 * HH];   // 4 KB: concat(h_f, h_b) for MLP
    __shared__ float  w1s[16 * 65];                        // padded stride 65 -> conflict-free
    __shared__ float  b1s[16], w2s[16];

    const int tid  = threadIdx.x;
    const int lane = tid & 31;
    const int warp = tid >> 5;
    const int wg   = blockIdx.x * WPB + warp;
    const int bb   = wg * P;                  // first batch row of this warp
    const int j    = lane;                    // hidden dim owned by this lane

    // ---- stage MLP weights (block-wide) ----
    for (int i = tid; i < 16 * 64; i += WPB * 32) {
        int u = i >> 6, k = i & 63;
        w1s[u * 65 + k] = W1[i];
    }
    if (tid < 16) { b1s[tid] = b1[tid]; w2s[tid] = W2[tid]; }

    // ---- stage x rows for this warp's 4 batches, transposed to float4-per-t ----
    for (int i = lane; i < TT; i += 32) {
        float a  = x[(bb + 0) * TT + i];
        float bq = x[(bb + 1) * TT + i];
        float c  = x[(bb + 2) * TT + i];
        float d  = x[(bb + 3) * TT + i];
        xs[warp][i] = make_float4(a, bq, c, d);
    }

    // ---- load recurrent weights: lane j owns rows j (r), j+32 (z), j+64 (n),
    //      pre-packed along K into f32x2 pairs ----
    u64 wr[16], wz[16], wn[16];
    {
        const float2* pr = (const float2*)(Whhf + (j)      * HH);
        const float2* pz = (const float2*)(Whhf + (j + 32) * HH);
        const float2* pn = (const float2*)(Whhf + (j + 64) * HH);
#pragma unroll
        for (int k = 0; k < 16; k++) {
            float2 t0 = pr[k]; wr[k] = pk2(t0.x, t0.y);
            float2 t1 = pz[k]; wz[k] = pk2(t1.x, t1.y);
            float2 t2 = pn[k]; wn[k] = pk2(t2.x, t2.y);
        }
    }
    const float wxr = Wihf[j], wxz = Wihf[j + 32], wxn = Wihf[j + 64];
    const float br   = bihf[j]      + bhhf[j];
    const float bz   = bihf[j + 32] + bhhf[j + 32];
    const float bn_i = bihf[j + 64];          // input-side n bias (outside r*)
    const float bn_h = bhhf[j + 64];          // hidden-side n bias (inside r*)

    // ---- init hidden state ----
    float h0 = 0.f, h1 = 0.f, h2 = 0.f, h3 = 0.f;
#pragma unroll
    for (int q = 0; q < P; q++) hbuf[warp][0][q][j] = 0.f;
    __syncwarp();

    const float4* xp = &xs[warp][0];
    int pp = 0;

    // ================= forward GRU scan =================
#pragma unroll 1
    for (int t = 0; t < TT; t++) {
        float4 xv = xp[t];
        // per-batch scalar terms: bias + x * W_ih
        float sr0 = fmaf(xv.x, wxr, br),   sr1 = fmaf(xv.y, wxr, br);
        float sr2 = fmaf(xv.z, wxr, br),   sr3 = fmaf(xv.w, wxr, br);
        float sz0 = fmaf(xv.x, wxz, bz),   sz1 = fmaf(xv.y, wxz, bz);
        float sz2 = fmaf(xv.z, wxz, bz),   sz3 = fmaf(xv.w, wxz, bz);
        float sn0 = fmaf(xv.x, wxn, bn_i), sn1 = fmaf(xv.y, wxn, bn_i);
        float sn2 = fmaf(xv.z, wxn, bn_i), sn3 = fmaf(xv.w, wxn, bn_i);

        const u64* hb = (const u64*)&hbuf[warp][pp][0][0];  // [q*16 + k]

        u64 g0 = hb[0], g1 = hb[16], g2 = hb[32], g3 = hb[48];
        u64 ar0 = fmul2(g0, wr[0]), az0 = fmul2(g0, wz[0]), an0 = fmul2(g0, wn[0]);
        u64 ar1 = fmul2(g1, wr[0]), az1 = fmul2(g1, wz[0]), an1 = fmul2(g1, wn[0]);
        u64 ar2 = fmul2(g2, wr[0]), az2 = fmul2(g2, wz[0]), an2 = fmul2(g2, wn[0]);
        u64 ar3 = fmul2(g3, wr[0]), az3 = fmul2(g3, wz[0]), an3 = fmul2(g3, wn[0]);
#pragma unroll
        for (int k = 1; k < 16; k++) {
            u64 q0 = hb[k], q1 = hb[16 + k], q2 = hb[32 + k], q3 = hb[48 + k];
            ar0 = ffma2(q0, wr[k], ar0); az0 = ffma2(q0, wz[k], az0); an0 = ffma2(q0, wn[k], an0);
            ar1 = ffma2(q1, wr[k], ar1); az1 = ffma2(q1, wz[k], az1); an1 = ffma2(q1, wn[k], an1);
            ar2 = ffma2(q2, wr[k], ar2); az2 = ffma2(q2, wz[k], az2); an2 = ffma2(q2, wn[k], an2);
            ar3 = ffma2(q3, wr[k], ar3); az3 = ffma2(q3, wz[k], az3); an3 = ffma2(q3, wn[k], an3);
        }

        h0 = gru_gate(ar0, az0, an0, sr0, sz0, sn0, bn_h, h0);
        h1 = gru_gate(ar1, az1, an1, sr1, sz1, sn1, bn_h, h1);
        h2 = gru_gate(ar2, az2, an2, sr2, sz2, sn2, bn_h, h2);
        h3 = gru_gate(ar3, az3, an3, sr3, sz3, sn3, bn_h, h3);

        float* hw = &hbuf[warp][pp ^ 1][0][0];
        hw[0 * HH + j] = h0;
        hw[1 * HH + j] = h1;
        hw[2 * HH + j] = h2;
        hw[3 * HH + j] = h3;
        pp ^= 1;
        __syncwarp();
    }

    // ================= backward GRU: exactly ONE step from h=0 =================
    // ys_b[T-1] consumes only x[T-1]; h@W_hh = 0, so it is elementwise.
    {
        float4 xl = xp[TT - 1];
        float xq[P] = { xl.x, xl.y, xl.z, xl.w };
        float hf[P] = { h0, h1, h2, h3 };
        const float wbr = Wihb[j], wbz = Wihb[j + 32], wbn = Wihb[j + 64];
        const float cbr  = bihb[j]      + bhhb[j];
        const float cbz  = bihb[j + 32] + bhhb[j + 32];
        const float cbni = bihb[j + 64];
        const float cbnh = bhhb[j + 64];
#pragma unroll
        for (int q = 0; q < P; q++) {
            float r = sigm(fmaf(xq[q], wbr, cbr));
            float z = sigm(fmaf(xq[q], wbz, cbz));
            float n = tanhfast(fmaf(r, cbnh, fmaf(xq[q], wbn, cbni)));
            float hbk = (1.0f - z) * n;
            vbuf[warp][q][j]      = hf[q];
            vbuf[warp][q][HH + j] = hbk;
        }
    }
    __syncthreads();   // w1s/b1s/w2s staged + vbuf written

    // ================= MLP head: relu(v@W1.T+b1) @ W2.T + b2 -> sigmoid =========
    {
        const int g = lane >> 4;     // two 16-lane groups -> two batches at once
        const int u = lane & 15;     // hidden unit
        const float b2v = __ldg(b2);
#pragma unroll
        for (int p2 = 0; p2 < 2; p2++) {
            int q = p2 * 2 + g;
            const float* v = &vbuf[warp][q][0];
            float acc = b1s[u];
#pragma unroll
            for (int k = 0; k < 64; k++)
                acc = fmaf(w1s[u * 65 + k], v[k], acc);
            acc = fmaxf(acc, 0.0f);
            float tt = acc * w2s[u];
            tt += __shfl_xor_sync(0xffffffffu, tt, 8);
            tt += __shfl_xor_sync(0xffffffffu, tt, 4);
            tt += __shfl_xor_sync(0xffffffffu, tt, 2);
            tt += __shfl_xor_sync(0xffffffffu, tt, 1);
            if (u == 0) out[bb + q] = sigm(tt + b2v);
        }
    }
}

extern "C" void kernel_launch(void* const* d_in, const int* in_sizes, int n_in,
                              void* d_out, int out_size) {
    const float* x    = (const float*)d_in[0];
    const float* Wihf = (const float*)d_in[1];
    const float* Whhf = (const float*)d_in[2];
    const float* bihf = (const float*)d_in[3];
    const float* bhhf = (const float*)d_in[4];
    const float* Wihb = (const float*)d_in[5];
    const float* Whhb = (const float*)d_in[6];
    const float* bihb = (const float*)d_in[7];
    const float* bhhb = (const float*)d_in[8];
    const float* W1   = (const float*)d_in[9];
    const float* b1   = (const float*)d_in[10];
    const float* W2   = (const float*)d_in[11];
    const float* b2   = (const float*)d_in[12];
    float* out = (float*)d_out;

    gru_bidir_kernel<<<NBLK, WPB * 32>>>(x, Wihf, Whhf, bihf, bhhf,
                                         Wihb, Whhb, bihb, bhhb,
                                         W1, b1, W2, b2, out);
}

// round 3
// speedup vs baseline: 1.0429x; 1.0429x over previous
#include <cuda_runtime.h>

#define NBLK 128
#define WPB  8        // warps per block -> 2 warps per SMSP
#define P    2        // batch rows per warp
#define TT   512
#define HH   32

typedef unsigned long long u64;

__device__ __forceinline__ u64 pk2(float a, float b) {
    u64 r; asm("mov.b64 %0,{%1,%2};" : "=l"(r) : "f"(a), "f"(b)); return r;
}
__device__ __forceinline__ void upk2(u64 v, float& a, float& b) {
    asm("mov.b64 {%0,%1},%2;" : "=f"(a), "=f"(b) : "l"(v));
}
__device__ __forceinline__ u64 ffma2(u64 a, u64 b, u64 c) {
    u64 d; asm("fma.rn.f32x2 %0,%1,%2,%3;" : "=l"(d) : "l"(a), "l"(b), "l"(c)); return d;
}
__device__ __forceinline__ u64 fmul2(u64 a, u64 b) {
    u64 d; asm("mul.rn.f32x2 %0,%1,%2;" : "=l"(d) : "l"(a), "l"(b)); return d;
}
__device__ __forceinline__ float ex2f(float x) {
    float y; asm("ex2.approx.f32 %0,%1;" : "=f"(y) : "f"(x)); return y;
}
__device__ __forceinline__ float rcpf(float x) {
    float y; asm("rcp.approx.f32 %0,%1;" : "=f"(y) : "f"(x)); return y;
}
// sigmoid(v) = 1/(1+exp(-v)) via ex2+rcp (~1e-6 accurate)
__device__ __forceinline__ float sigm(float v) {
    return rcpf(1.0f + ex2f(v * -1.4426950408889634f));
}
// tanh(v) = 2/(1+exp(-2v)) - 1
__device__ __forceinline__ float tanhfast(float v) {
    float s = rcpf(1.0f + ex2f(v * -2.8853900817779268f));
    return fmaf(2.0f, s, -1.0f);
}

// one GRU gate update for one batch element, given k-packed partial sums
__device__ __forceinline__ float gru_gate(u64 ar, u64 az, u64 an,
                                          float sr, float sz, float sn,
                                          float bn_h, float hprev) {
    float lo, hi;
    upk2(ar, lo, hi); float r = sigm(lo + hi + sr);
    upk2(az, lo, hi); float z = sigm(lo + hi + sz);
    upk2(an, lo, hi); float hn = lo + hi + bn_h;
    float n = tanhfast(fmaf(r, hn, sn));
    return fmaf(z, hprev - n, n);   // (1-z)*n + z*h
}

__global__ void __launch_bounds__(WPB * 32, 1)
gru_bidir_kernel(const float* __restrict__ x,
                 const float* __restrict__ Wihf, const float* __restrict__ Whhf,
                 const float* __restrict__ bihf, const float* __restrict__ bhhf,
                 const float* __restrict__ Wihb, const float* __restrict__ Whhb,
                 const float* __restrict__ bihb, const float* __restrict__ bhhb,
                 const float* __restrict__ W1,  const float* __restrict__ b1,
                 const float* __restrict__ W2,  const float* __restrict__ b2,
                 float* __restrict__ out)
{
    __shared__ float2 xs[WPB][TT];                         // 32 KB: x staged per warp (2 batches)
    __shared__ __align__(16) float hbuf[WPB][2][P][HH];    // 2 KB: ping-pong hidden (read as u64)
    __shared__ __align__(16) float vbuf[WPB][P][2 * HH];   // 4 KB: concat(h_f, h_b) for MLP
    __shared__ float  w1s[16 * 65];                        // padded stride 65 -> conflict-free
    __shared__ float  b1s[16], w2s[16];

    const int tid  = threadIdx.x;
    const int lane = tid & 31;
    const int warp = tid >> 5;
    const int wg   = blockIdx.x * WPB + warp;
    const int bb   = wg * P;                  // first batch row of this warp
    const int j    = lane;                    // hidden dim owned by this lane

    // ---- stage MLP weights (block-wide) ----
    for (int i = tid; i < 16 * 64; i += WPB * 32) {
        int u = i >> 6, k = i & 63;
        w1s[u * 65 + k] = W1[i];
    }
    if (tid < 16) { b1s[tid] = b1[tid]; w2s[tid] = W2[tid]; }

    // ---- stage x rows for this warp's 2 batches, transposed to float2-per-t ----
    for (int i = lane; i < TT; i += 32) {
        float a  = x[(bb + 0) * TT + i];
        float bq = x[(bb + 1) * TT + i];
        xs[warp][i] = make_float2(a, bq);
    }

    // ---- load recurrent weights: lane j owns rows j (r), j+32 (z), j+64 (n),
    //      pre-packed along K into f32x2 pairs ----
    u64 wr[16], wz[16], wn[16];
    {
        const float2* pr = (const float2*)(Whhf + (j)      * HH);
        const float2* pz = (const float2*)(Whhf + (j + 32) * HH);
        const float2* pn = (const float2*)(Whhf + (j + 64) * HH);
#pragma unroll
        for (int k = 0; k < 16; k++) {
            float2 t0 = pr[k]; wr[k] = pk2(t0.x, t0.y);
            float2 t1 = pz[k]; wz[k] = pk2(t1.x, t1.y);
            float2 t2 = pn[k]; wn[k] = pk2(t2.x, t2.y);
        }
    }
    const float wxr = Wihf[j], wxz = Wihf[j + 32], wxn = Wihf[j + 64];
    const float br   = bihf[j]      + bhhf[j];
    const float bz   = bihf[j + 32] + bhhf[j + 32];
    const float bn_i = bihf[j + 64];          // input-side n bias (outside r*)
    const float bn_h = bhhf[j + 64];          // hidden-side n bias (inside r*)

    // ---- init hidden state ----
    float h0 = 0.f, h1 = 0.f;
#pragma unroll
    for (int q = 0; q < P; q++) hbuf[warp][0][q][j] = 0.f;
    __syncwarp();

    const float2* xp = &xs[warp][0];
    int pp = 0;

    // ================= forward GRU scan =================
#pragma unroll 1
    for (int t = 0; t < TT; t++) {
        float2 xv = xp[t];
        // per-batch scalar terms: bias + x * W_ih
        float sr0 = fmaf(xv.x, wxr, br),   sr1 = fmaf(xv.y, wxr, br);
        float sz0 = fmaf(xv.x, wxz, bz),   sz1 = fmaf(xv.y, wxz, bz);
        float sn0 = fmaf(xv.x, wxn, bn_i), sn1 = fmaf(xv.y, wxn, bn_i);

        const u64* hb = (const u64*)&hbuf[warp][pp][0][0];  // [q*16 + k]

        u64 g0 = hb[0], g1 = hb[16];
        u64 ar0 = fmul2(g0, wr[0]), az0 = fmul2(g0, wz[0]), an0 = fmul2(g0, wn[0]);
        u64 ar1 = fmul2(g1, wr[0]), az1 = fmul2(g1, wz[0]), an1 = fmul2(g1, wn[0]);
#pragma unroll
        for (int k = 1; k < 16; k++) {
            u64 q0 = hb[k], q1 = hb[16 + k];
            ar0 = ffma2(q0, wr[k], ar0); az0 = ffma2(q0, wz[k], az0); an0 = ffma2(q0, wn[k], an0);
            ar1 = ffma2(q1, wr[k], ar1); az1 = ffma2(q1, wz[k], az1); an1 = ffma2(q1, wn[k], an1);
        }

        h0 = gru_gate(ar0, az0, an0, sr0, sz0, sn0, bn_h, h0);
        h1 = gru_gate(ar1, az1, an1, sr1, sz1, sn1, bn_h, h1);

        float* hw = &hbuf[warp][pp ^ 1][0][0];
        hw[0 * HH + j] = h0;
        hw[1 * HH + j] = h1;
        pp ^= 1;
        __syncwarp();
    }

    // ================= backward GRU: exactly ONE step from h=0 =================
    // ys_b[T-1] consumes only x[T-1]; h@W_hh = 0, so it is elementwise.
    {
        float2 xl = xp[TT - 1];
        float xq[P] = { xl.x, xl.y };
        float hf[P] = { h0, h1 };
        const float wbr = Wihb[j], wbz = Wihb[j + 32], wbn = Wihb[j + 64];
        const float cbr  = bihb[j]      + bhhb[j];
        const float cbz  = bihb[j + 32] + bhhb[j + 32];
        const float cbni = bihb[j + 64];
        const float cbnh = bhhb[j + 64];
#pragma unroll
        for (int q = 0; q < P; q++) {
            float r = sigm(fmaf(xq[q], wbr, cbr));
            float z = sigm(fmaf(xq[q], wbz, cbz));
            float n = tanhfast(fmaf(r, cbnh, fmaf(xq[q], wbn, cbni)));
            float hbk = (1.0f - z) * n;
            vbuf[warp][q][j]      = hf[q];
            vbuf[warp][q][HH + j] = hbk;
        }
    }
    __syncthreads();   // w1s/b1s/w2s staged + vbuf written

    // ================= MLP head: relu(v@W1.T+b1) @ W2.T + b2 -> sigmoid =========
    {
        const int g = lane >> 4;     // two 16-lane groups -> one batch each
        const int u = lane & 15;     // hidden unit
        const float b2v = __ldg(b2);
        const int q = g;
        const float* v = &vbuf[warp][q][0];
        float acc = b1s[u];
#pragma unroll
        for (int k = 0; k < 64; k++)
            acc = fmaf(w1s[u * 65 + k], v[k], acc);
        acc = fmaxf(acc, 0.0f);
        float tt = acc * w2s[u];
        tt += __shfl_xor_sync(0xffffffffu, tt, 8);
        tt += __shfl_xor_sync(0xffffffffu, tt, 4);
        tt += __shfl_xor_sync(0xffffffffu, tt, 2);
        tt += __shfl_xor_sync(0xffffffffu, tt, 1);
        if (u == 0) out[bb + q] = sigm(tt + b2v);
    }
}

extern "C" void kernel_launch(void* const* d_in, const int* in_sizes, int n_in,
                              void* d_out, int out_size) {
    const float* x    = (const float*)d_in[0];
    const float* Wihf = (const float*)d_in[1];
    const float* Whhf = (const float*)d_in[2];
    const float* bihf = (const float*)d_in[3];
    const float* bhhf = (const float*)d_in[4];
    const float* Wihb = (const float*)d_in[5];
    const float* Whhb = (const float*)d_in[6];
    const float* bihb = (const float*)d_in[7];
    const float* bhhb = (const float*)d_in[8];
    const float* W1   = (const float*)d_in[9];
    const float* b1   = (const float*)d_in[10];
    const float* W2   = (const float*)d_in[11];
    const float* b2   = (const float*)d_in[12];
    float* out = (float*)d_out;

    gru_bidir_kernel<<<NBLK, WPB * 32>>>(x, Wihf, Whhf, bihf, bhhf,
                                         Wihb, Whhb, bihb, bhhb,
                                         W1, b1, W2, b2, out);
}

// round 4
// speedup vs baseline: 1.1242x; 1.0779x over previous
#include <cuda_runtime.h>

#define NBLK 128
#define WPB  16       // warps per block -> 4 warps per SMSP
#define P    1        // batch rows per warp
#define TT   512
#define HH   32

typedef unsigned long long u64;

__device__ __forceinline__ u64 pk2(float a, float b) {
    u64 r; asm("mov.b64 %0,{%1,%2};" : "=l"(r) : "f"(a), "f"(b)); return r;
}
__device__ __forceinline__ void upk2(u64 v, float& a, float& b) {
    asm("mov.b64 {%0,%1},%2;" : "=f"(a), "=f"(b) : "l"(v));
}
__device__ __forceinline__ u64 ffma2(u64 a, u64 b, u64 c) {
    u64 d; asm("fma.rn.f32x2 %0,%1,%2,%3;" : "=l"(d) : "l"(a), "l"(b), "l"(c)); return d;
}
__device__ __forceinline__ u64 fmul2(u64 a, u64 b) {
    u64 d; asm("mul.rn.f32x2 %0,%1,%2;" : "=l"(d) : "l"(a), "l"(b)); return d;
}
__device__ __forceinline__ float ex2f(float x) {
    float y; asm("ex2.approx.f32 %0,%1;" : "=f"(y) : "f"(x)); return y;
}
__device__ __forceinline__ float rcpf(float x) {
    float y; asm("rcp.approx.f32 %0,%1;" : "=f"(y) : "f"(x)); return y;
}
// plain (unscaled) versions for the one-off backward step
__device__ __forceinline__ float sigm(float v) {
    return rcpf(1.0f + ex2f(v * -1.4426950408889634f));
}
__device__ __forceinline__ float tanhfast(float v) {
    float s = rcpf(1.0f + ex2f(v * -2.8853900817779268f));
    return fmaf(2.0f, s, -1.0f);
}
// pre-scaled versions: argument already multiplied by -log2e (sigm) / -2log2e (tanh)
__device__ __forceinline__ float sigm_s(float vs) {   // vs = -log2(e)*v
    return rcpf(1.0f + ex2f(vs));
}
__device__ __forceinline__ float tanh_s(float vs) {   // vs = -2*log2(e)*v
    return fmaf(2.0f, rcpf(1.0f + ex2f(vs)), -1.0f);
}

#define NL2E  (-1.4426950408889634f)   // -log2(e)
#define N2L2E (-2.8853900817779268f)   // -2*log2(e)

__global__ void __launch_bounds__(WPB * 32, 1)
gru_bidir_kernel(const float* __restrict__ x,
                 const float* __restrict__ Wihf, const float* __restrict__ Whhf,
                 const float* __restrict__ bihf, const float* __restrict__ bhhf,
                 const float* __restrict__ Wihb, const float* __restrict__ Whhb,
                 const float* __restrict__ bihb, const float* __restrict__ bhhb,
                 const float* __restrict__ W1,  const float* __restrict__ b1,
                 const float* __restrict__ W2,  const float* __restrict__ b2,
                 float* __restrict__ out)
{
    __shared__ float xs[WPB][TT];                          // 32 KB: x staged, 1 batch/warp
    __shared__ __align__(16) float hbuf[WPB][2][HH];       // 4 KB: ping-pong hidden (read as u64)
    __shared__ __align__(16) float vbuf[WPB][2 * HH];      // 4 KB: concat(h_f, h_b) for MLP
    __shared__ float  w1s[16 * 65];                        // padded stride 65 -> conflict-free
    __shared__ float  b1s[16], w2s[16];

    const int tid  = threadIdx.x;
    const int lane = tid & 31;
    const int warp = tid >> 5;
    const int bb   = blockIdx.x * WPB + warp;  // batch row owned by this warp
    const int j    = lane;                     // hidden dim owned by this lane

    // ---- stage MLP weights (block-wide) ----
    for (int i = tid; i < 16 * 64; i += WPB * 32) {
        int u = i >> 6, k = i & 63;
        w1s[u * 65 + k] = W1[i];
    }
    if (tid < 16) { b1s[tid] = b1[tid]; w2s[tid] = W2[tid]; }

    // ---- stage this warp's x row ----
    for (int i = lane; i < TT; i += 32)
        xs[warp][i] = x[bb * TT + i];

    // ---- load recurrent weights, PRE-SCALED so gate args land already scaled:
    //      r,z rows * -log2e ; n rows * -2log2e.  K-packed into f32x2 pairs. ----
    u64 wr[16], wz[16], wn[16];
    {
        const float2* pr = (const float2*)(Whhf + (j)      * HH);
        const float2* pz = (const float2*)(Whhf + (j + 32) * HH);
        const float2* pn = (const float2*)(Whhf + (j + 64) * HH);
#pragma unroll
        for (int k = 0; k < 16; k++) {
            float2 t0 = pr[k]; wr[k] = pk2(t0.x * NL2E,  t0.y * NL2E);
            float2 t1 = pz[k]; wz[k] = pk2(t1.x * NL2E,  t1.y * NL2E);
            float2 t2 = pn[k]; wn[k] = pk2(t2.x * N2L2E, t2.y * N2L2E);
        }
    }
    const float wxr = Wihf[j] * NL2E, wxz = Wihf[j + 32] * NL2E, wxn = Wihf[j + 64] * N2L2E;
    const float br   = (bihf[j]      + bhhf[j])      * NL2E;
    const float bz   = (bihf[j + 32] + bhhf[j + 32]) * NL2E;
    const float bn_i = bihf[j + 64] * N2L2E;     // input-side n bias (outside r*), scaled
    const float bn_h = bhhf[j + 64] * N2L2E;     // hidden-side n bias (inside r*), scaled

    // ---- init hidden state ----
    float h = 0.f;
    hbuf[warp][0][j] = 0.f;
    __syncwarp();

    const float* xp = &xs[warp][0];
    int pp = 0;

    // ================= forward GRU scan =================
#pragma unroll 1
    for (int t = 0; t < TT; t++) {
        float xv = xp[t];
        float sr = fmaf(xv, wxr, br);     // scaled by -log2e
        float sz = fmaf(xv, wxz, bz);
        float sn = fmaf(xv, wxn, bn_i);   // scaled by -2log2e

        const u64* hb = (const u64*)&hbuf[warp][pp][0];

        u64 g0 = hb[0];
        u64 ar = fmul2(g0, wr[0]), az = fmul2(g0, wz[0]), an = fmul2(g0, wn[0]);
#pragma unroll
        for (int k = 1; k < 16; k++) {
            u64 q0 = hb[k];
            ar = ffma2(q0, wr[k], ar);
            az = ffma2(q0, wz[k], az);
            an = ffma2(q0, wn[k], an);
        }

        float lo, hi;
        upk2(ar, lo, hi); float r  = sigm_s(lo + hi + sr);
        upk2(az, lo, hi); float z  = sigm_s(lo + hi + sz);
        upk2(an, lo, hi); float hn = lo + hi + bn_h;           // scaled hidden n-part
        float n = tanh_s(fmaf(r, hn, sn));
        h = fmaf(z, h - n, n);            // (1-z)*n + z*h

        hbuf[warp][pp ^ 1][j] = h;
        pp ^= 1;
        __syncwarp();
    }

    // ================= backward GRU: exactly ONE step from h=0 =================
    // ys_b[T-1] consumes only x[T-1]; h@W_hh = 0, so it is elementwise.
    {
        float xq = xp[TT - 1];
        const float wbr = Wihb[j], wbz = Wihb[j + 32], wbn = Wihb[j + 64];
        const float cbr  = bihb[j]      + bhhb[j];
        const float cbz  = bihb[j + 32] + bhhb[j + 32];
        const float cbni = bihb[j + 64];
        const float cbnh = bhhb[j + 64];
        float r = sigm(fmaf(xq, wbr, cbr));
        float z = sigm(fmaf(xq, wbz, cbz));
        float n = tanhfast(fmaf(r, cbnh, fmaf(xq, wbn, cbni)));
        float hbk = (1.0f - z) * n;
        vbuf[warp][j]      = h;
        vbuf[warp][HH + j] = hbk;
    }
    __syncthreads();   // w1s/b1s/w2s staged + vbuf written

    // ================= MLP head: relu(v@W1.T+b1) @ W2.T + b2 -> sigmoid =========
    if (lane < 16) {
        const int u = lane;          // hidden unit
        const float b2v = __ldg(b2);
        const float* v = &vbuf[warp][0];
        float acc = b1s[u];
#pragma unroll
        for (int k = 0; k < 64; k++)
            acc = fmaf(w1s[u * 65 + k], v[k], acc);
        acc = fmaxf(acc, 0.0f);
        float tt = acc * w2s[u];
        tt += __shfl_xor_sync(0x0000ffffu, tt, 8, 16);
        tt += __shfl_xor_sync(0x0000ffffu, tt, 4, 16);
        tt += __shfl_xor_sync(0x0000ffffu, tt, 2, 16);
        tt += __shfl_xor_sync(0x0000ffffu, tt, 1, 16);
        if (u == 0) out[bb] = sigm(tt + b2v);
    }
}

extern "C" void kernel_launch(void* const* d_in, const int* in_sizes, int n_in,
                              void* d_out, int out_size) {
    const float* x    = (const float*)d_in[0];
    const float* Wihf = (const float*)d_in[1];
    const float* Whhf = (const float*)d_in[2];
    const float* bihf = (const float*)d_in[3];
    const float* bhhf = (const float*)d_in[4];
    const float* Wihb = (const float*)d_in[5];
    const float* Whhb = (const float*)d_in[6];
    const float* bihb = (const float*)d_in[7];
    const float* bhhb = (const float*)d_in[8];
    const float* W1   = (const float*)d_in[9];
    const float* b1   = (const float*)d_in[10];
    const float* W2   = (const float*)d_in[11];
    const float* b2   = (const float*)d_in[12];
    float* out = (float*)d_out;

    gru_bidir_kernel<<<NBLK, WPB * 32>>>(x, Wihf, Whhf, bihf, bhhf,
                                         Wihb, Whhb, bihb, bhhb,
                                         W1, b1, W2, b2, out);
}